// round 5
// baseline (speedup 1.0000x reference)
#include <cuda_runtime.h>
#include <cuda_fp16.h>
#include <cstdint>
#include <cmath>

// ============================================================================
// Problem constants
// ============================================================================
#define BATCH  16384
#define DIN    1024
#define DFEAT  4096
#define DEG    3

// GEMM tiling
#define TM 128
#define TN 128
#define BK 32          // 32 halves; combined row = [hi 64B | lo 64B] = 128B (SW128)
#define NK (DIN / BK)  // 32 K-chunks
#define STAGES 3

#define KTILE_BYTES  (TM * 128)             // 16384: 128 rows x 128B combined hi|lo
#define STAGE_BYTES  (4 * KTILE_BYTES)      // A + 3 B combined tiles = 65536
#define SMEM_TILES   1024
#define SMEM_TOTAL   (SMEM_TILES + STAGES * STAGE_BYTES)   // 197632

// SMEM control offsets
#define OFF_TMEM     0
#define OFF_EMPTY(s) (16 + 8 * (s))
#define OFF_MMADONE  48

// TMEM layout: three fp32 accumulators, 128 cols each
#define TMEM_D(d) ((d) * 128)
#define TMEM_COLS 512

// idesc for tcgen05.mma kind::f16: dtype=F32 (bit4), atype=F16(0), btype=F16(0),
// N>>3 at [17:22], M>>4 at [24:28]
static constexpr uint32_t MMA_IDESC =
    (1u << 4) | ((TN / 8) << 17) | ((TM / 16) << 24);

// ============================================================================
// Scratch (device globals -- sanctioned, no runtime allocation)
// x split: x*exp(-ll) = xh + xl (fp16 two-term). W split likewise, transposed.
// ============================================================================
__device__ __half g_xh[(size_t)BATCH * DIN];
__device__ __half g_xl[(size_t)BATCH * DIN];
__device__ __half g_wh[(size_t)DEG * DFEAT * DIN];   // [d][o][i]
__device__ __half g_wl[(size_t)DEG * DFEAT * DIN];

// ============================================================================
// Helpers legal on ALL targets
// ============================================================================
__device__ __forceinline__ uint32_t smem_u32(const void* p) {
    uint32_t a;
    asm("{ .reg .u64 t; cvta.to.shared.u64 t, %1; cvt.u32.u64 %0, t; }"
        : "=r"(a) : "l"(p));
    return a;
}

#define CP_ASYNC16(dst, src) \
    asm volatile("cp.async.cg.shared.global [%0], [%1], 16;" \
                 :: "r"(dst), "l"(src) : "memory")
#define CP_COMMIT() asm volatile("cp.async.commit_group;" ::: "memory")
#define CP_WAIT(n)  asm volatile("cp.async.wait_group %0;" :: "n"(n) : "memory")

#define SWZ128(off) ((off) ^ (((off) >> 3) & 0x70))

// ============================================================================
// Pre-pass 1: x -> (hi, lo) fp16 pair, scaled by exp(-log_lengthscale)
// ============================================================================
__global__ void convert_x_kernel(const float* __restrict__ x,
                                 const float* __restrict__ lls) {
    float s = expf(-lls[0]);
    size_t idx = ((size_t)blockIdx.x * blockDim.x + threadIdx.x) * 4;
    float4 v = *reinterpret_cast<const float4*>(x + idx);
    float f[4] = {v.x * s, v.y * s, v.z * s, v.w * s};
    __half hi[4], lo[4];
    #pragma unroll
    for (int j = 0; j < 4; j++) {
        hi[j] = __float2half_rn(f[j]);
        lo[j] = __float2half_rn(f[j] - __half2float(hi[j]));
    }
    *reinterpret_cast<uint2*>(g_xh + idx) = *reinterpret_cast<uint2*>(hi);
    *reinterpret_cast<uint2*>(g_xl + idx) = *reinterpret_cast<uint2*>(lo);
}

// ============================================================================
// Pre-pass 2: W [d][i][o] fp32 -> transposed (hi, lo) fp16 pairs [d][o][i]
// ============================================================================
__global__ void convert_w_kernel(const float* __restrict__ W) {
    __shared__ float tile[32][33];
    int d  = blockIdx.z;
    int o0 = blockIdx.x * 32;
    int i0 = blockIdx.y * 32;
    int tx = threadIdx.x, ty = threadIdx.y;
    tile[ty][tx] = W[((size_t)d * DIN + (i0 + ty)) * DFEAT + (o0 + tx)];
    __syncthreads();
    float f = tile[tx][ty];
    __half hi = __float2half_rn(f);
    __half lo = __float2half_rn(f - __half2float(hi));
    size_t o = ((size_t)d * DFEAT + (o0 + ty)) * DIN + (i0 + tx);
    g_wh[o] = hi;
    g_wl[o] = lo;
}

// ============================================================================
// Main fused kernel: 3-term fp16 split GEMM (hi*hi + lo*hi + hi*lo) per degree,
// three fp32 TMEM accumulators, fused product epilogue.
//   Accel pass (compute_103a/100a): tcgen05 + TMEM.
//   Base pass (compute_103): cp.async + ldmatrix + mma.sync with same split.
// ============================================================================
__global__ void __launch_bounds__(128, 1)
sketch_kernel(float* __restrict__ out, const float* __restrict__ lv) {
#if defined(__CUDA_ARCH_FEAT_SM103_ALL) || defined(__CUDA_ARCH_FEAT_SM100_ALL)
    // ------------------------------------------------------------------
    // tcgen05 path
    // ------------------------------------------------------------------
    extern __shared__ char smem[];
    uint32_t sb = smem_u32(smem);
    int tid = threadIdx.x;
    int wid = tid >> 5, lid = tid & 31;
    int n0 = blockIdx.x * TN;
    int m0 = blockIdx.y * TM;

    if (wid == 0) {
        asm volatile("tcgen05.alloc.cta_group::1.sync.aligned.shared::cta.b32 [%0], %1;"
                     :: "r"(sb + OFF_TMEM), "r"((uint32_t)TMEM_COLS) : "memory");
        asm volatile("tcgen05.relinquish_alloc_permit.cta_group::1.sync.aligned;");
    }
    if (tid == 0) {
        #pragma unroll
        for (int s = 0; s < STAGES; s++) {
            asm volatile("mbarrier.init.shared.b64 [%0], %1;"
                         :: "r"(sb + OFF_EMPTY(s)), "r"(1) : "memory");
        }
        asm volatile("mbarrier.init.shared.b64 [%0], %1;"
                     :: "r"(sb + OFF_MMADONE), "r"(1) : "memory");
    }
    __syncthreads();
    uint32_t tmem;
    asm volatile("ld.shared.b32 %0, [%1];" : "=r"(tmem) : "r"(sb + OFF_TMEM));

    #define MBAR_WAIT(addr, parity) do {                                           \
        uint32_t _m = (addr), _p = (parity), _d;                                   \
        asm volatile("{ .reg .pred p; "                                            \
            "mbarrier.try_wait.parity.acquire.cta.shared::cta.b64 p, [%1], %2; "   \
            "selp.b32 %0, 1, 0, p; }" : "=r"(_d) : "r"(_m), "r"(_p) : "memory");   \
        if (!_d) {                                                                 \
            asm volatile("{ .reg .pred P; L_%=: "                                  \
                "mbarrier.try_wait.parity.acquire.cta.shared::cta.b64 P, [%0], %1, 0x989680; " \
                "@P bra.uni D_%=; bra.uni L_%=; D_%=: }"                           \
                :: "r"(_m), "r"(_p) : "memory");                                   \
        }                                                                          \
    } while (0)

    // Stage loader: combined [hi|lo] rows. Tile = 128 rows x 8 chunks of 16B;
    // chunks 0-3 = hi halves (k bytes 0..63), chunks 4-7 = lo halves.
    auto load_stage = [&](int s, int kt) {
        uint32_t base = sb + SMEM_TILES + s * STAGE_BYTES;
        const __half* ah = g_xh + (size_t)m0 * DIN + kt * BK;
        const __half* al = g_xl + (size_t)m0 * DIN + kt * BK;
        #pragma unroll
        for (int c = tid; c < 1024; c += 128) {
            int row = c >> 3, ch = c & 7;
            uint32_t off = (uint32_t)(row << 7) | (uint32_t)(ch << 4);
            const __half* src = (ch < 4) ? (ah + (size_t)row * DIN + ch * 8)
                                         : (al + (size_t)row * DIN + (ch - 4) * 8);
            CP_ASYNC16(base + SWZ128(off), src);
        }
        #pragma unroll
        for (int d = 0; d < DEG; d++) {
            const __half* bh = g_wh + ((size_t)d * DFEAT + n0) * DIN + kt * BK;
            const __half* bl = g_wl + ((size_t)d * DFEAT + n0) * DIN + kt * BK;
            uint32_t tb = base + (1 + d) * KTILE_BYTES;
            #pragma unroll
            for (int c = tid; c < 1024; c += 128) {
                int row = c >> 3, ch = c & 7;
                uint32_t off = (uint32_t)(row << 7) | (uint32_t)(ch << 4);
                const __half* src = (ch < 4) ? (bh + (size_t)row * DIN + ch * 8)
                                             : (bl + (size_t)row * DIN + (ch - 4) * 8);
                CP_ASYNC16(tb + SWZ128(off), src);
            }
        }
    };

    // K-major SW128 descriptor: LBO=1 (16B), SBO=64 (1024B), version 1
    constexpr uint64_t DESC_BASE =
        (uint64_t(2) << 61) | (uint64_t(1) << 46) | (uint64_t(64) << 32) | (uint64_t(1) << 16);

    // Prologue: keep STAGES-1 = 2 K-chunks in flight
    load_stage(0, 0);
    CP_COMMIT();
    load_stage(1, 1);
    CP_COMMIT();

    for (int kt = 0; kt < NK; kt++) {
        int s = kt % STAGES;

        CP_WAIT(STAGES - 2);
        __syncthreads();   // stage s tiles visible to all threads

        if (wid == 0) {
            uint32_t is_elect;
            asm volatile("{ .reg .pred p; elect.sync _|p, 0xFFFFFFFF; selp.b32 %0, 1, 0, p; }"
                         : "=r"(is_elect));
            if (is_elect) {
                asm volatile("fence.proxy.async.shared::cta;" ::: "memory");
                uint32_t stage_base = sb + SMEM_TILES + s * STAGE_BYTES;
                uint64_t ad = DESC_BASE | ((uint64_t)(stage_base >> 4) & 0x3FFF);
                #pragma unroll
                for (int d = 0; d < DEG; d++) {
                    uint32_t bb = stage_base + (1 + d) * KTILE_BYTES;
                    uint64_t bd = DESC_BASE | ((uint64_t)(bb >> 4) & 0x3FFF);
                    #pragma unroll
                    for (int ks = 0; ks < 2; ks++) {   // two k16 steps in BK=32
                        // hi * hi  (zero-init only on very first dispatch per degree)
                        uint32_t acc0 = (kt > 0 || ks > 0) ? 1u : 0u;
                        asm volatile(
                            "{ .reg .pred p; setp.ne.u32 p, %5, 0;"
                            "tcgen05.mma.cta_group::1.kind::f16 [%0], %1, %2, %3, {%4, %4, %4, %4}, p; }"
                            :: "r"(tmem + TMEM_D(d)), "l"(ad + ks * 2),
                               "l"(bd + ks * 2), "r"(MMA_IDESC), "r"(0u), "r"(acc0)
                            : "memory");
                        // lo * hi  (A lo half at +64B = +4 desc units)
                        asm volatile(
                            "{ .reg .pred p; setp.ne.u32 p, %5, 0;"
                            "tcgen05.mma.cta_group::1.kind::f16 [%0], %1, %2, %3, {%4, %4, %4, %4}, p; }"
                            :: "r"(tmem + TMEM_D(d)), "l"(ad + 4 + ks * 2),
                               "l"(bd + ks * 2), "r"(MMA_IDESC), "r"(0u), "r"(1u)
                            : "memory");
                        // hi * lo  (B lo half at +64B)
                        asm volatile(
                            "{ .reg .pred p; setp.ne.u32 p, %5, 0;"
                            "tcgen05.mma.cta_group::1.kind::f16 [%0], %1, %2, %3, {%4, %4, %4, %4}, p; }"
                            :: "r"(tmem + TMEM_D(d)), "l"(ad + ks * 2),
                               "l"(bd + 4 + ks * 2), "r"(MMA_IDESC), "r"(0u), "r"(1u)
                            : "memory");
                    }
                }
                if (kt == NK - 1)
                    asm volatile("tcgen05.commit.cta_group::1.mbarrier::arrive::one.shared::cluster.b64 [%0];"
                                 :: "r"(sb + OFF_MMADONE) : "memory");
                else
                    asm volatile("tcgen05.commit.cta_group::1.mbarrier::arrive::one.shared::cluster.b64 [%0];"
                                 :: "r"(sb + OFF_EMPTY(s)) : "memory");
            }
        }

        // Prefetch K-chunk kt+2 into stage ns, gated on that stage's MMA done.
        int nk2 = kt + STAGES - 1;
        if (nk2 < NK) {
            int ns = nk2 % STAGES;
            int c = nk2 / STAGES;
            if (c > 0) MBAR_WAIT(sb + OFF_EMPTY(ns), (c - 1) & 1);
            load_stage(ns, nk2);
            CP_COMMIT();
        }
    }

    // Epilogue: wait all MMAs, multiply the three projections, scale, store
    MBAR_WAIT(sb + OFF_MMADONE, 0);
    asm volatile("tcgen05.fence::after_thread_sync;" ::: "memory");

    float scale = 0.015625f * expf(0.5f * lv[0]);   // 1/sqrt(4096) * exp(0.5*lv)
    float* orow = out + (size_t)(m0 + wid * 32 + lid) * DFEAT + n0;

    #define TC_LD_X32(r, tmem_addr) \
        asm volatile( \
            "tcgen05.ld.sync.aligned.32x32b.x32.b32 " \
            "{%0, %1, %2, %3, %4, %5, %6, %7, " \
            " %8, %9, %10, %11, %12, %13, %14, %15, " \
            " %16, %17, %18, %19, %20, %21, %22, %23, " \
            " %24, %25, %26, %27, %28, %29, %30, %31}, [%32];" \
            : "=r"((r)[0]),  "=r"((r)[1]),  "=r"((r)[2]),  "=r"((r)[3]), \
              "=r"((r)[4]),  "=r"((r)[5]),  "=r"((r)[6]),  "=r"((r)[7]), \
              "=r"((r)[8]),  "=r"((r)[9]),  "=r"((r)[10]), "=r"((r)[11]), \
              "=r"((r)[12]), "=r"((r)[13]), "=r"((r)[14]), "=r"((r)[15]), \
              "=r"((r)[16]), "=r"((r)[17]), "=r"((r)[18]), "=r"((r)[19]), \
              "=r"((r)[20]), "=r"((r)[21]), "=r"((r)[22]), "=r"((r)[23]), \
              "=r"((r)[24]), "=r"((r)[25]), "=r"((r)[26]), "=r"((r)[27]), \
              "=r"((r)[28]), "=r"((r)[29]), "=r"((r)[30]), "=r"((r)[31]) \
            : "r"(tmem_addr))

    #pragma unroll
    for (int c = 0; c < TN / 32; c++) {
        uint32_t r0[32], r1[32], r2[32];
        TC_LD_X32(r0, tmem + TMEM_D(0) + c * 32);
        TC_LD_X32(r1, tmem + TMEM_D(1) + c * 32);
        TC_LD_X32(r2, tmem + TMEM_D(2) + c * 32);
        asm volatile("tcgen05.wait::ld.sync.aligned;" ::: "memory");
        float f[32];
        #pragma unroll
        for (int j = 0; j < 32; j++) {
            f[j] = __uint_as_float(r0[j]) * __uint_as_float(r1[j]) *
                   __uint_as_float(r2[j]) * scale;
        }
        #pragma unroll
        for (int q = 0; q < 8; q++) {
            float4 v = make_float4(f[q * 4], f[q * 4 + 1], f[q * 4 + 2], f[q * 4 + 3]);
            *reinterpret_cast<float4*>(orow + c * 32 + q * 4) = v;
        }
    }

    asm volatile("tcgen05.fence::before_thread_sync;" ::: "memory");
    __syncthreads();
    if (wid == 0) {
        asm volatile("tcgen05.dealloc.cta_group::1.sync.aligned.b32 %0, %1;"
                     :: "r"(tmem), "r"((uint32_t)TMEM_COLS));
    }
    #undef MBAR_WAIT
    #undef TC_LD_X32

#else
    // ------------------------------------------------------------------
    // Fallback path: cp.async + ldmatrix + mma.sync with the SAME 3-term
    // fp16 split. 4 n-passes of 32 cols; 3-stage cp.async pipeline; BK=32.
    // ------------------------------------------------------------------
    extern __shared__ char smem[];
    uint32_t sb = smem_u32(smem);
    int tid  = threadIdx.x;
    int wid  = tid >> 5;
    int lane = tid & 31;
    int n0 = blockIdx.x * TN;
    int m0 = blockIdx.y * TM;

    float scale = 0.015625f * expf(0.5f * lv[0]);

    // Stage layout identical to accel: A combined tile + 3 B combined tiles
    // (B tiles only rows 0..31 populated = this pass's n-slice).
    auto load_stage_fb = [&](int s, int kt, int p) {
        uint32_t base = sb + SMEM_TILES + s * STAGE_BYTES;
        const __half* ah = g_xh + (size_t)m0 * DIN + kt * BK;
        const __half* al = g_xl + (size_t)m0 * DIN + kt * BK;
        #pragma unroll
        for (int c = tid; c < 1024; c += 128) {
            int row = c >> 3, ch = c & 7;
            uint32_t off = (uint32_t)(row << 7) | (uint32_t)(ch << 4);
            const __half* src = (ch < 4) ? (ah + (size_t)row * DIN + ch * 8)
                                         : (al + (size_t)row * DIN + (ch - 4) * 8);
            CP_ASYNC16(base + SWZ128(off), src);
        }
        #pragma unroll
        for (int d = 0; d < DEG; d++) {
            size_t brow = (size_t)d * DFEAT + n0 + 32 * p;
            const __half* bh = g_wh + brow * DIN + kt * BK;
            const __half* bl = g_wl + brow * DIN + kt * BK;
            uint32_t tb = base + (1 + d) * KTILE_BYTES;
            #pragma unroll
            for (int j = 0; j < 2; j++) {
                int c = tid + 128 * j;          // 0..255 -> 32 rows x 8 chunks
                int row = c >> 3, ch = c & 7;
                uint32_t off = (uint32_t)(row << 7) | (uint32_t)(ch << 4);
                const __half* src = (ch < 4) ? (bh + (size_t)row * DIN + ch * 8)
                                             : (bl + (size_t)row * DIN + (ch - 4) * 8);
                CP_ASYNC16(tb + SWZ128(off), src);
            }
        }
    };

    int lr = lane & 15;        // ldmatrix row-within-16
    int lc = lane >> 4;        // k8 half selector

    for (int p = 0; p < 4; p++) {
        float acc[DEG][2][4][4];
        #pragma unroll
        for (int d = 0; d < DEG; d++)
            #pragma unroll
            for (int mt = 0; mt < 2; mt++)
                #pragma unroll
                for (int nt = 0; nt < 4; nt++)
                    #pragma unroll
                    for (int r = 0; r < 4; r++) acc[d][mt][nt][r] = 0.0f;

        #pragma unroll
        for (int s = 0; s < STAGES - 1; s++) {
            load_stage_fb(s, s, p);
            CP_COMMIT();
        }

        for (int kt = 0; kt < NK; kt++) {
            CP_WAIT(STAGES - 2);
            __syncthreads();
            int s = kt % STAGES;
            uint32_t abase = sb + SMEM_TILES + s * STAGE_BYTES;

            #pragma unroll
            for (int ks = 0; ks < 2; ks++) {
                // A fragments hi & lo: rows 32*wid + 16*mt + lr; hi at byte 0, lo at 64
                uint32_t a_hi[2][4], a_lo[2][4];
                #pragma unroll
                for (int mt = 0; mt < 2; mt++) {
                    uint32_t row = 32 * wid + 16 * mt + lr;
                    uint32_t byt = (uint32_t)(ks * 32 + lc * 16);
                    uint32_t addr_h = abase + SWZ128((row << 7) | byt);
                    uint32_t addr_l = abase + SWZ128((row << 7) | (64 + byt));
                    asm volatile(
                        "ldmatrix.sync.aligned.m8n8.x4.shared.b16 {%0,%1,%2,%3}, [%4];"
                        : "=r"(a_hi[mt][0]), "=r"(a_hi[mt][1]), "=r"(a_hi[mt][2]), "=r"(a_hi[mt][3])
                        : "r"(addr_h));
                    asm volatile(
                        "ldmatrix.sync.aligned.m8n8.x4.shared.b16 {%0,%1,%2,%3}, [%4];"
                        : "=r"(a_lo[mt][0]), "=r"(a_lo[mt][1]), "=r"(a_lo[mt][2]), "=r"(a_lo[mt][3])
                        : "r"(addr_l));
                }
                #pragma unroll
                for (int d = 0; d < DEG; d++) {
                    uint32_t bbase = abase + (1 + d) * KTILE_BYTES;
                    uint32_t b_hi[2][4], b_lo[2][4];
                    #pragma unroll
                    for (int h = 0; h < 2; h++) {
                        uint32_t row = 16 * h + lr;
                        uint32_t byt = (uint32_t)(ks * 32 + lc * 16);
                        uint32_t addr_h = bbase + SWZ128((row << 7) | byt);
                        uint32_t addr_l = bbase + SWZ128((row << 7) | (64 + byt));
                        asm volatile(
                            "ldmatrix.sync.aligned.m8n8.x4.shared.b16 {%0,%1,%2,%3}, [%4];"
                            : "=r"(b_hi[h][0]), "=r"(b_hi[h][1]), "=r"(b_hi[h][2]), "=r"(b_hi[h][3])
                            : "r"(addr_h));
                        asm volatile(
                            "ldmatrix.sync.aligned.m8n8.x4.shared.b16 {%0,%1,%2,%3}, [%4];"
                            : "=r"(b_lo[h][0]), "=r"(b_lo[h][1]), "=r"(b_lo[h][2]), "=r"(b_lo[h][3])
                            : "r"(addr_l));
                    }
                    #pragma unroll
                    for (int mt = 0; mt < 2; mt++) {
                        #pragma unroll
                        for (int nt = 0; nt < 4; nt++) {
                            int h = nt >> 1, lo = nt & 1;
                            float* c = acc[d][mt][nt];
                            asm volatile(   // hi*hi
                                "mma.sync.aligned.m16n8k16.row.col.f32.f16.f16.f32 "
                                "{%0,%1,%2,%3}, {%4,%5,%6,%7}, {%8,%9}, {%0,%1,%2,%3};"
                                : "+f"(c[0]), "+f"(c[1]), "+f"(c[2]), "+f"(c[3])
                                : "r"(a_hi[mt][0]), "r"(a_hi[mt][1]), "r"(a_hi[mt][2]), "r"(a_hi[mt][3]),
                                  "r"(b_hi[h][lo]), "r"(b_hi[h][lo + 2]));
                            asm volatile(   // lo*hi
                                "mma.sync.aligned.m16n8k16.row.col.f32.f16.f16.f32 "
                                "{%0,%1,%2,%3}, {%4,%5,%6,%7}, {%8,%9}, {%0,%1,%2,%3};"
                                : "+f"(c[0]), "+f"(c[1]), "+f"(c[2]), "+f"(c[3])
                                : "r"(a_lo[mt][0]), "r"(a_lo[mt][1]), "r"(a_lo[mt][2]), "r"(a_lo[mt][3]),
                                  "r"(b_hi[h][lo]), "r"(b_hi[h][lo + 2]));
                            asm volatile(   // hi*lo
                                "mma.sync.aligned.m16n8k16.row.col.f32.f16.f16.f32 "
                                "{%0,%1,%2,%3}, {%4,%5,%6,%7}, {%8,%9}, {%0,%1,%2,%3};"
                                : "+f"(c[0]), "+f"(c[1]), "+f"(c[2]), "+f"(c[3])
                                : "r"(a_hi[mt][0]), "r"(a_hi[mt][1]), "r"(a_hi[mt][2]), "r"(a_hi[mt][3]),
                                  "r"(b_lo[h][lo]), "r"(b_lo[h][lo + 2]));
                        }
                    }
                }
            }
            __syncthreads();
            int nk = kt + STAGES - 1;
            if (nk < NK) load_stage_fb(nk % STAGES, nk, p);
            CP_COMMIT();
        }
        CP_WAIT(0);
        __syncthreads();

        // epilogue for this n-pass
        int g = lane >> 2, t = lane & 3;
        #pragma unroll
        for (int mt = 0; mt < 2; mt++) {
            #pragma unroll
            for (int nt = 0; nt < 4; nt++) {
                int row = m0 + 32 * wid + 16 * mt + g;
                int col = n0 + 32 * p + 8 * nt + 2 * t;
                float p0 = acc[0][mt][nt][0] * acc[1][mt][nt][0] * acc[2][mt][nt][0] * scale;
                float p1 = acc[0][mt][nt][1] * acc[1][mt][nt][1] * acc[2][mt][nt][1] * scale;
                float p2 = acc[0][mt][nt][2] * acc[1][mt][nt][2] * acc[2][mt][nt][2] * scale;
                float p3 = acc[0][mt][nt][3] * acc[1][mt][nt][3] * acc[2][mt][nt][3] * scale;
                *reinterpret_cast<float2*>(out + (size_t)row * DFEAT + col) =
                    make_float2(p0, p1);
                *reinterpret_cast<float2*>(out + (size_t)(row + 8) * DFEAT + col) =
                    make_float2(p2, p3);
            }
        }
    }
#endif
}

// ============================================================================
// Launch
// ============================================================================
extern "C" void kernel_launch(void* const* d_in, const int* in_sizes, int n_in,
                              void* d_out, int out_size) {
    const float* x   = (const float*)d_in[0];
    const float* W   = (const float*)d_in[1];
    const float* lls = (const float*)d_in[2];
    const float* lv  = (const float*)d_in[3];
    float* out = (float*)d_out;

    convert_x_kernel<<<(BATCH * (size_t)DIN) / (4 * 256), 256>>>(x, lls);
    convert_w_kernel<<<dim3(DFEAT / 32, DIN / 32, DEG), dim3(32, 32)>>>(W);

    cudaFuncSetAttribute(sketch_kernel,
                         cudaFuncAttributeMaxDynamicSharedMemorySize, SMEM_TOTAL);
    sketch_kernel<<<dim3(DFEAT / TN, BATCH / TM), 128, SMEM_TOTAL>>>(out, lv);
}